// round 15
// baseline (speedup 1.0000x reference)
#include <cuda_runtime.h>
#include <cuda_fp16.h>
#include <math.h>

// Problem constants (CrossAttention_24008867184861)
#define BQ   2
#define SQ   2048
#define SK   2048
#define HQ   16
#define HKV  4
#define GRP  (HQ / HKV)
#define DH   64
#define NEGV (-10000.0f)
#define SCALE 0.125f
#define LOG2E 1.4426950408889634f

#define TM 128            // Q rows per CTA-job
#define TN 64             // K cols per tile
#define THREADS 256
#define KPAD 72           // f16 row stride (144B: 16B-aligned, ldmatrix conflict-free)
#define NJOBS (32 * (SQ / TM))   // 512 (bh x qt)
#define NPERS 296                // persistent CTAs (148 SMs x 2)

__device__ float g_maskBias[BQ * SK];                  // 0 valid, NEGV padded
__device__ float g_bsum[BQ * HKV][16][DH];             // V sums per 128-row block
__device__ int   g_jobctr;                             // persistent work queue
#define KVN ((size_t)BQ * HKV * SK * DH)
__device__ __align__(16) __half g_k16[KVN];            // rn16(K), [bh][s][d]
__device__ __align__(16) __half g_v16[KVN];            // rn16(V), [bh][s][d]

// ---------------------------------------------------------------------------
static __device__ __forceinline__ unsigned smem_u32(const void* p) {
    return (unsigned)__cvta_generic_to_shared(p);
}
#define LDSM4(r0, r1, r2, r3, addr)                                            \
    asm volatile("ldmatrix.sync.aligned.m8n8.x4.shared.b16 {%0,%1,%2,%3}, [%4];" \
                 : "=r"(r0), "=r"(r1), "=r"(r2), "=r"(r3) : "r"(addr))
#define LDSM4T(r0, r1, r2, r3, addr)                                           \
    asm volatile("ldmatrix.sync.aligned.m8n8.x4.trans.shared.b16 {%0,%1,%2,%3}, [%4];" \
                 : "=r"(r0), "=r"(r1), "=r"(r2), "=r"(r3) : "r"(addr))
#define MMA16816(c, a0, a1, a2, a3, b0, b1)                                    \
    asm volatile("mma.sync.aligned.m16n8k16.row.col.f32.f16.f16.f32 "          \
                 "{%0,%1,%2,%3}, {%4,%5,%6,%7}, {%8,%9}, {%0,%1,%2,%3};"       \
                 : "+f"((c)[0]), "+f"((c)[1]), "+f"((c)[2]), "+f"((c)[3])      \
                 : "r"(a0), "r"(a1), "r"(a2), "r"(a3), "r"(b0), "r"(b1))
#define CP16(dst_u32, src_ptr)                                                 \
    asm volatile("cp.async.ca.shared.global [%0], [%1], 16;"                   \
                 :: "r"(dst_u32), "l"(src_ptr))
#define CP_COMMIT() asm volatile("cp.async.commit_group;")
#define CP_WAIT0()  asm volatile("cp.async.wait_group 0;")

// exp2 via magic-constant range reduction; x <= 0 (finite). rel err ~6e-5.
static __device__ __forceinline__ float exp2m(float x) {
    float xc = fmaxf(x, -127.0f);
    float z  = xc + 12582912.0f;            // 1.5 * 2^23: RN integer round
    float f  = xc - (z - 12582912.0f);      // f in [-0.5, 0.5]
    int   e  = (__float_as_int(z) + (127 - 0x4B400000)) << 23;
    float sc = __int_as_float(e);
    float p = fmaf(f, 0.00961812911f, 0.0555041087f);
    p = fmaf(f, p, 0.240226507f);
    p = fmaf(f, p, 0.693147181f);
    p = fmaf(f, p, 1.0f);
    return sc * p;
}
static __device__ __forceinline__ void split16(float x, __half& hi, __half& lo) {
    hi = __float2half_rn(x);
    lo = __float2half_rn(x - __half2float(hi));
}

// ---------------------------------------------------------------------------
// Merged prologue (one launch, 640 blocks):
//   blocks [0,512): K,V fp32 -> fp16 [bh][s][d]
//   blocks [512,640): per-128-row-block V sums + mask expand + job ctr reset
// ---------------------------------------------------------------------------
__global__ void __launch_bounds__(256)
prologue_kernel(const float* __restrict__ kv, const void* __restrict__ mask) {
    const int tid = threadIdx.x;

    if (blockIdx.x < 512) {
        const int tot = BQ * HKV * SK * (DH / 4);
        for (int t = blockIdx.x * 256 + tid; t < tot; t += 512 * 256) {
            int d4 = t & 15;
            int s  = (t >> 4) & (SK - 1);
            int hk = (t >> 15) & 3;
            int b  = t >> 17;
            size_t ksrc = (((size_t)(b * SK + s) * 2) * HKV + hk) * DH + d4 * 4;
            size_t dst  = (((size_t)(b * HKV + hk)) * SK + s) * DH + d4 * 4;
            float4 k4 = *(const float4*)(kv + ksrc);
            float4 v4 = *(const float4*)(kv + ksrc + (size_t)HKV * DH);
            *(__half2*)&g_k16[dst]     = __floats2half2_rn(k4.x, k4.y);
            *(__half2*)&g_k16[dst + 2] = __floats2half2_rn(k4.z, k4.w);
            *(__half2*)&g_v16[dst]     = __floats2half2_rn(v4.x, v4.y);
            *(__half2*)&g_v16[dst + 2] = __floats2half2_rn(v4.z, v4.w);
        }
        return;
    }

    // ---- V block sums: 128 blocks = bh(8) x blk(16); 256 thr = 4 rows x 64 d
    const int bk  = blockIdx.x - 512;
    const int bh  = bk >> 4, blk = bk & 15;
    const int b   = bh >> 2, hkv = bh & 3;
    const int d   = tid & 63;
    const int rg  = tid >> 6;             // 0..3

    __shared__ float ps[4][64];
    float acc = 0.0f;
#pragma unroll 4
    for (int i = 0; i < 32; i++) {
        int row = blk * 128 + i * 4 + rg;
        acc += kv[(((size_t)(b * SK + row) * 2 + 1) * HKV + hkv) * DH + d];
    }
    ps[rg][d] = acc;
    __syncthreads();
    if (tid < 64)
        g_bsum[bh][blk][d] = (ps[0][d] + ps[1][d]) + (ps[2][d] + ps[3][d]);

    if (bk == 0) {
        if (tid == 0) g_jobctr = 0;       // reset persistent work queue
        const unsigned char* mb = (const unsigned char*)mask;
        bool odd = false;
        for (int i = tid; i < BQ * SK; i += 256)
            if ((i & 3) && mb[i]) odd = true;
        bool is_byte = __syncthreads_or(odd);
        const int* mi = (const int*)mask;
        for (int i = tid; i < BQ * SK; i += 256)
            g_maskBias[i] = (is_byte ? (int)mb[i] : mi[i]) ? 0.0f : NEGV;
    }
}

// ---------------------------------------------------------------------------
// Smem layout (halves units):
//   Qhs[128][72]  Qls[128][72]                      (36864 B)
//   2 stages x { Khs[64][72], Vs[64][72], bias[64]f } (2 x 18688 B)
// Total 74240 B -> 2 CTAs/SM.
// ---------------------------------------------------------------------------
#define OFF_QH    0
#define OFF_QL    (TM * KPAD)
#define OFF_ST    (2 * TM * KPAD)
#define ST_K      0
#define ST_V      (TN * KPAD)
#define ST_BIAS   (2 * TN * KPAD)
#define STAGE_HALFS (2 * TN * KPAD + 2 * TN)   // 9344
#define SMEM_HALFS (OFF_ST + 2 * STAGE_HALFS)

// cp.async f16 K/V tile + fp32 bias directly into operand layout.
static __device__ __forceinline__ void issue_tile(__half* smp, int stage, int n0,
                                                  size_t bhbase, int b, int tid) {
    __half* st = smp + OFF_ST + stage * STAGE_HALFS;
#pragma unroll
    for (int k = 0; k < 4; k++) {
        int i = tid + k * THREADS;          // 0..1023; k<2 -> K, k>=2 -> V
        int within = i & 511;
        int r = within >> 3, c = within & 7;
        const __half* src = (i < 512 ? g_k16 : g_v16) + bhbase + (size_t)(n0 + r) * DH + c * 8;
        __half* dst = st + (i < 512 ? ST_K : ST_V) + r * KPAD + c * 8;
        CP16(smem_u32(dst), src);
    }
    if (tid < 16)
        CP16(smem_u32((float*)(st + ST_BIAS) + tid * 4),
             &g_maskBias[b * SK + n0 + tid * 4]);
}

__global__ void __launch_bounds__(THREADS, 2)
fa_kernel(const float* __restrict__ q, float* __restrict__ out) {
    extern __shared__ __align__(16) __half smp[];
    __half (*Qhs)[KPAD] = (__half (*)[KPAD])(smp + OFF_QH);
    __half (*Qls)[KPAD] = (__half (*)[KPAD])(smp + OFF_QL);
    __shared__ int s_job;

    const int tid  = threadIdx.x;
    const int lane = tid & 31;
    const int w    = tid >> 5;
    const int qd   = lane & 3;
    const int rl   = lane >> 2;
    const int g    = lane >> 3;
    const int arow = w * 16 + (lane & 15);
    const int acol = (lane >> 4) * 8;

    for (;;) {
        __syncthreads();                   // smem (Q + stages + s_job) free
        if (tid == 0) s_job = atomicAdd(&g_jobctr, 1);
        __syncthreads();
        const int job = s_job;
        if (job >= NJOBS) break;

        // heavy-first job order: qt descending, all bh within a qt level
        const int qt  = (SQ / TM - 1) - (job >> 5);
        const int bh  = job & 31;
        const int b   = bh >> 4;
        const int h   = bh & 15;
        const int hkv = h / GRP;
        const int m0  = qt * TM;
        const size_t bhbase = ((size_t)(b * HKV + hkv)) * SK * DH;
        const int ntiles = 2 * qt + 2;

        // kick off tile 0 loads, overlap with Q load+split
        issue_tile(smp, 0, 0, bhbase, b, tid);
        CP_COMMIT();

        const float* qg = q + ((size_t)(b * SQ + m0) * HQ + h) * DH;
        for (int i = tid; i < TM * 16; i += THREADS) {
            int r = i >> 4, f = i & 15;
            float4 v = *(const float4*)(qg + (size_t)r * HQ * DH + f * 4);
            __half h0, l0, h1, l1, h2, l2, h3, l3;
            split16(v.x, h0, l0); split16(v.y, h1, l1);
            split16(v.z, h2, l2); split16(v.w, h3, l3);
            *(__half2*)&Qhs[r][f * 4]     = __halves2half2(h0, h1);
            *(__half2*)&Qhs[r][f * 4 + 2] = __halves2half2(h2, h3);
            *(__half2*)&Qls[r][f * 4]     = __halves2half2(l0, l1);
            *(__half2*)&Qls[r][f * 4 + 2] = __halves2half2(l2, l3);
        }

        float m_lo = -1e30f, m_hi = -1e30f, l_lo = 0.0f, l_hi = 0.0f;
        float O[8][4];
#pragma unroll
        for (int j = 0; j < 8; j++)
#pragma unroll
            for (int e = 0; e < 4; e++) O[j][e] = 0.0f;

        const int r_lo = m0 + w * 16 + rl;
        const int r_hi = r_lo + 8;

        for (int jt = 0; jt < ntiles; jt++) {
            const int n0 = jt * TN;
            const int stage = jt & 1;
            __half* st = smp + OFF_ST + stage * STAGE_HALFS;
            __half (*Khs)[KPAD] = (__half (*)[KPAD])(st + ST_K);
            __half (*Vs)[KPAD]  = (__half (*)[KPAD])(st + ST_V);
            float* biasS = (float*)(st + ST_BIAS);

            // tile jt landed; barrier also proves stage^1 consumed
            CP_WAIT0();
            __syncthreads();
            if (jt + 1 < ntiles) {
                issue_tile(smp, stage ^ 1, n0 + TN, bhbase, b, tid);
                CP_COMMIT();
            }

            // ---- S = Q K^T via 2-pass compensated HMMA (Qh*Kh + Ql*Kh) ----
            float S[8][4];
#pragma unroll
            for (int j = 0; j < 8; j++)
#pragma unroll
                for (int e = 0; e < 4; e++) S[j][e] = 0.0f;

#pragma unroll
            for (int ks = 0; ks < 4; ks++) {
                unsigned ah0, ah1, ah2, ah3, al0, al1, al2, al3;
                LDSM4(ah0, ah1, ah2, ah3, smem_u32(&Qhs[arow][ks * 16 + acol]));
                LDSM4(al0, al1, al2, al3, smem_u32(&Qls[arow][ks * 16 + acol]));
#pragma unroll
                for (int jp = 0; jp < 4; jp++) {
                    const int brow = jp * 16 + (g >> 1) * 8 + (lane & 7);
                    const int bcol = ks * 16 + (g & 1) * 8;
                    unsigned bh0, bh1, bh2, bh3;
                    LDSM4(bh0, bh1, bh2, bh3, smem_u32(&Khs[brow][bcol]));
                    MMA16816(S[2 * jp],     ah0, ah1, ah2, ah3, bh0, bh1);
                    MMA16816(S[2 * jp + 1], ah0, ah1, ah2, ah3, bh2, bh3);
                    MMA16816(S[2 * jp],     al0, al1, al2, al3, bh0, bh1);
                    MMA16816(S[2 * jp + 1], al0, al1, al2, al3, bh2, bh3);
                }
            }

            // ---- scale + bias (+ causal only on the last two tiles) ----
            float mx_lo = -1e30f, mx_hi = -1e30f;
            if (jt < 2 * qt) {             // fast path: no causal masking
#pragma unroll
                for (int j = 0; j < 8; j++) {
                    float2 bp = *(float2*)&biasS[j * 8 + qd * 2];
                    float s0 = fmaf(S[j][0], SCALE, bp.x);
                    float s1 = fmaf(S[j][1], SCALE, bp.y);
                    float s2 = fmaf(S[j][2], SCALE, bp.x);
                    float s3 = fmaf(S[j][3], SCALE, bp.y);
                    S[j][0] = s0; S[j][1] = s1; S[j][2] = s2; S[j][3] = s3;
                    mx_lo = fmaxf(mx_lo, fmaxf(s0, s1));
                    mx_hi = fmaxf(mx_hi, fmaxf(s2, s3));
                }
            } else {                       // diagonal tiles: apply causal mask
#pragma unroll
                for (int j = 0; j < 8; j++) {
                    float2 bp = *(float2*)&biasS[j * 8 + qd * 2];
                    int c0 = n0 + j * 8 + qd * 2, c1 = c0 + 1;
                    float s0 = fmaf(S[j][0], SCALE, bp.x);
                    float s1 = fmaf(S[j][1], SCALE, bp.y);
                    float s2 = fmaf(S[j][2], SCALE, bp.x);
                    float s3 = fmaf(S[j][3], SCALE, bp.y);
                    if (c0 > r_lo) s0 = NEGV;
                    if (c1 > r_lo) s1 = NEGV;
                    if (c0 > r_hi) s2 = NEGV;
                    if (c1 > r_hi) s3 = NEGV;
                    S[j][0] = s0; S[j][1] = s1; S[j][2] = s2; S[j][3] = s3;
                    mx_lo = fmaxf(mx_lo, fmaxf(s0, s1));
                    mx_hi = fmaxf(mx_hi, fmaxf(s2, s3));
                }
            }
            mx_lo = fmaxf(mx_lo, __shfl_xor_sync(0xffffffffu, mx_lo, 1));
            mx_lo = fmaxf(mx_lo, __shfl_xor_sync(0xffffffffu, mx_lo, 2));
            mx_hi = fmaxf(mx_hi, __shfl_xor_sync(0xffffffffu, mx_hi, 1));
            mx_hi = fmaxf(mx_hi, __shfl_xor_sync(0xffffffffu, mx_hi, 2));

            float mn_lo = fmaxf(m_lo, mx_lo), mn_hi = fmaxf(m_hi, mx_hi);

            // ---- alpha rescale, skipped when no row in the warp has a new max
            if (__any_sync(0xffffffffu, (mn_lo > m_lo) || (mn_hi > m_hi))) {
                float al = exp2m((m_lo - mn_lo) * LOG2E);
                float ah = exp2m((m_hi - mn_hi) * LOG2E);
                l_lo *= al; l_hi *= ah;
#pragma unroll
                for (int j = 0; j < 8; j++) {
                    O[j][0] *= al; O[j][1] *= al;
                    O[j][2] *= ah; O[j][3] *= ah;
                }
                m_lo = mn_lo; m_hi = mn_hi;
            }

            float base_lo = -m_lo * LOG2E, base_hi = -m_hi * LOG2E;
            float sum_lo = 0.0f, sum_hi = 0.0f;
            unsigned pf[8][2];
#pragma unroll
            for (int j = 0; j < 8; j++) {
                float p0 = exp2m(fmaf(S[j][0], LOG2E, base_lo));
                float p1 = exp2m(fmaf(S[j][1], LOG2E, base_lo));
                float p2 = exp2m(fmaf(S[j][2], LOG2E, base_hi));
                float p3 = exp2m(fmaf(S[j][3], LOG2E, base_hi));
                sum_lo += p0 + p1;
                sum_hi += p2 + p3;
                __half2 hl = __floats2half2_rn(p0, p1);
                __half2 hh = __floats2half2_rn(p2, p3);
                pf[j][0] = *(unsigned*)&hl;
                pf[j][1] = *(unsigned*)&hh;
            }
            sum_lo += __shfl_xor_sync(0xffffffffu, sum_lo, 1);
            sum_lo += __shfl_xor_sync(0xffffffffu, sum_lo, 2);
            sum_hi += __shfl_xor_sync(0xffffffffu, sum_hi, 1);
            sum_hi += __shfl_xor_sync(0xffffffffu, sum_hi, 2);
            l_lo += sum_lo;
            l_hi += sum_hi;

            // ---- O += P V via HMMA (P frags from registers) ----
#pragma unroll
            for (int ks = 0; ks < 4; ks++) {
                unsigned A0 = pf[2 * ks][0], A1 = pf[2 * ks][1];
                unsigned A2 = pf[2 * ks + 1][0], A3 = pf[2 * ks + 1][1];
#pragma unroll
                for (int dp = 0; dp < 4; dp++) {
                    unsigned b0, b1, b2, b3;
                    unsigned vaddr = smem_u32(&Vs[ks * 16 + (g & 1) * 8 + (lane & 7)][(dp * 2 + (g >> 1)) * 8]);
                    LDSM4T(b0, b1, b2, b3, vaddr);
                    MMA16816(O[2 * dp],     A0, A1, A2, A3, b0, b1);
                    MMA16816(O[2 * dp + 1], A0, A1, A2, A3, b2, b3);
                }
            }
        }

        // ---- epilogue: tail correction over UNPROCESSED cols only ----
        const int n_proc = ntiles * TN;   // m0 + 128, multiple of 128
        bool need = (m_lo < -5000.0f) || (m_hi < -5000.0f);
        if (__any_sync(0xffffffffu, need) && n_proc < SK) {
            float mf_lo = fmaxf(m_lo, NEGV), mf_hi = fmaxf(m_hi, NEGV);
            float al = __expf(m_lo - mf_lo), ah = __expf(m_hi - mf_hi);
            float te_lo = __expf(NEGV - mf_lo), te_hi = __expf(NEGV - mf_hi);
            float ntail = (float)(SK - n_proc);
            l_lo = l_lo * al + ntail * te_lo;
            l_hi = l_hi * ah + ntail * te_hi;
            const int blk0 = n_proc >> 7;
            const int bhk  = b * HKV + hkv;
#pragma unroll
            for (int j = 0; j < 8; j++) {
                int d0 = j * 8 + qd * 2;
                float t0 = 0.0f, t1 = 0.0f;
                for (int bb = blk0; bb < 16; bb++) {
                    t0 += g_bsum[bhk][bb][d0];
                    t1 += g_bsum[bhk][bb][d0 + 1];
                }
                O[j][0] = O[j][0] * al + te_lo * t0;
                O[j][1] = O[j][1] * al + te_lo * t1;
                O[j][2] = O[j][2] * ah + te_hi * t0;
                O[j][3] = O[j][3] * ah + te_hi * t1;
            }
        }

        float il = 1.0f / l_lo, ih = 1.0f / l_hi;
        float* po  = out + ((size_t)(b * SQ + r_lo) * HQ + h) * DH;
        float* po2 = out + ((size_t)(b * SQ + r_hi) * HQ + h) * DH;
#pragma unroll
        for (int j = 0; j < 8; j++) {
            int d0 = j * 8 + qd * 2;
            *(float2*)&po[d0]  = make_float2(O[j][0] * il, O[j][1] * il);
            *(float2*)&po2[d0] = make_float2(O[j][2] * ih, O[j][3] * ih);
        }
    }
}

// ---------------------------------------------------------------------------
extern "C" void kernel_launch(void* const* d_in, const int* in_sizes, int n_in,
                              void* d_out, int out_size) {
    const float* q    = (const float*)d_in[0];
    const float* kv   = (const float*)d_in[1];
    const void*  mask = d_in[2];
    float* out = (float*)d_out;

    const int smem_bytes = SMEM_HALFS * sizeof(__half);   // 74240
    static bool attr_set = false;
    if (!attr_set) {
        cudaFuncSetAttribute(fa_kernel,
                             cudaFuncAttributeMaxDynamicSharedMemorySize,
                             smem_bytes);
        attr_set = true;
    }

    prologue_kernel<<<640, 256>>>(kv, mask);
    fa_kernel<<<NPERS, THREADS, smem_bytes>>>(q, out);
}

// round 17
// speedup vs baseline: 1.3797x; 1.3797x over previous
#include <cuda_runtime.h>
#include <cuda_fp16.h>
#include <math.h>

// Problem constants (CrossAttention_24008867184861)
#define BQ   2
#define SQ   2048
#define SK   2048
#define HQ   16
#define HKV  4
#define GRP  (HQ / HKV)
#define DH   64
#define NEGV (-10000.0f)
#define SCALE 0.125f
#define LOG2E 1.4426950408889634f

#define TM 128            // Q rows per CTA
#define TN 64             // K cols per tile
#define THREADS 256
#define KPAD 72           // f16 row stride (144B: 16B-aligned, ldmatrix conflict-free)

__device__ float g_maskBias[BQ * SK];                  // 0 valid, NEGV padded
__device__ float g_bsum[BQ * HKV][16][DH];             // V sums per 128-row block
#define KVN ((size_t)BQ * HKV * SK * DH)
__device__ __align__(16) __half g_k16[KVN];            // rn16(K), [bh][s][d]
__device__ __align__(16) __half g_v16[KVN];            // rn16(V), [bh][s][d]

// ---------------------------------------------------------------------------
static __device__ __forceinline__ unsigned smem_u32(const void* p) {
    return (unsigned)__cvta_generic_to_shared(p);
}
#define LDSM4(r0, r1, r2, r3, addr)                                            \
    asm volatile("ldmatrix.sync.aligned.m8n8.x4.shared.b16 {%0,%1,%2,%3}, [%4];" \
                 : "=r"(r0), "=r"(r1), "=r"(r2), "=r"(r3) : "r"(addr))
#define LDSM4T(r0, r1, r2, r3, addr)                                           \
    asm volatile("ldmatrix.sync.aligned.m8n8.x4.trans.shared.b16 {%0,%1,%2,%3}, [%4];" \
                 : "=r"(r0), "=r"(r1), "=r"(r2), "=r"(r3) : "r"(addr))
#define MMA16816(c, a0, a1, a2, a3, b0, b1)                                    \
    asm volatile("mma.sync.aligned.m16n8k16.row.col.f32.f16.f16.f32 "          \
                 "{%0,%1,%2,%3}, {%4,%5,%6,%7}, {%8,%9}, {%0,%1,%2,%3};"       \
                 : "+f"((c)[0]), "+f"((c)[1]), "+f"((c)[2]), "+f"((c)[3])      \
                 : "r"(a0), "r"(a1), "r"(a2), "r"(a3), "r"(b0), "r"(b1))
#define CP16(dst_u32, src_ptr)                                                 \
    asm volatile("cp.async.ca.shared.global [%0], [%1], 16;"                   \
                 :: "r"(dst_u32), "l"(src_ptr))
#define CP_COMMIT() asm volatile("cp.async.commit_group;")
#define CP_WAIT0()  asm volatile("cp.async.wait_group 0;")

// exp2 via magic-constant range reduction; x <= 0 (finite). rel err ~6e-5.
static __device__ __forceinline__ float exp2m(float x) {
    float xc = fmaxf(x, -127.0f);
    float z  = xc + 12582912.0f;            // 1.5 * 2^23: RN integer round
    float f  = xc - (z - 12582912.0f);      // f in [-0.5, 0.5]
    int   e  = (__float_as_int(z) + (127 - 0x4B400000)) << 23;
    float sc = __int_as_float(e);
    float p = fmaf(f, 0.00961812911f, 0.0555041087f);
    p = fmaf(f, p, 0.240226507f);
    p = fmaf(f, p, 0.693147181f);
    p = fmaf(f, p, 1.0f);
    return sc * p;
}
static __device__ __forceinline__ void split16(float x, __half& hi, __half& lo) {
    hi = __float2half_rn(x);
    lo = __float2half_rn(x - __half2float(hi));
}

// ---------------------------------------------------------------------------
// Merged prologue (one launch, 640 blocks):
//   blocks [0,512): K,V fp32 -> fp16 [bh][s][d]
//   blocks [512,640): per-128-row-block V sums (coalesced) + mask expand
// ---------------------------------------------------------------------------
__global__ void __launch_bounds__(256)
prologue_kernel(const float* __restrict__ kv, const void* __restrict__ mask) {
    const int tid = threadIdx.x;

    if (blockIdx.x < 512) {
        const int tot = BQ * HKV * SK * (DH / 4);
        for (int t = blockIdx.x * 256 + tid; t < tot; t += 512 * 256) {
            int d4 = t & 15;
            int s  = (t >> 4) & (SK - 1);
            int hk = (t >> 15) & 3;
            int b  = t >> 17;
            size_t ksrc = (((size_t)(b * SK + s) * 2) * HKV + hk) * DH + d4 * 4;
            size_t dst  = (((size_t)(b * HKV + hk)) * SK + s) * DH + d4 * 4;
            float4 k4 = *(const float4*)(kv + ksrc);
            float4 v4 = *(const float4*)(kv + ksrc + (size_t)HKV * DH);
            *(__half2*)&g_k16[dst]     = __floats2half2_rn(k4.x, k4.y);
            *(__half2*)&g_k16[dst + 2] = __floats2half2_rn(k4.z, k4.w);
            *(__half2*)&g_v16[dst]     = __floats2half2_rn(v4.x, v4.y);
            *(__half2*)&g_v16[dst + 2] = __floats2half2_rn(v4.z, v4.w);
        }
        return;
    }

    // ---- V block sums: 128 blocks = bh(8) x blk(16); 256 thr = 4 rows x 64 d
    const int bk  = blockIdx.x - 512;
    const int bh  = bk >> 4, blk = bk & 15;
    const int b   = bh >> 2, hkv = bh & 3;
    const int d   = tid & 63;
    const int rg  = tid >> 6;             // 0..3

    __shared__ float ps[4][64];
    float acc = 0.0f;
#pragma unroll 4
    for (int i = 0; i < 32; i++) {
        int row = blk * 128 + i * 4 + rg;
        acc += kv[(((size_t)(b * SK + row) * 2 + 1) * HKV + hkv) * DH + d];
    }
    ps[rg][d] = acc;
    __syncthreads();
    if (tid < 64)
        g_bsum[bh][blk][d] = (ps[0][d] + ps[1][d]) + (ps[2][d] + ps[3][d]);

    if (bk == 0) {
        const unsigned char* mb = (const unsigned char*)mask;
        bool odd = false;
        for (int i = tid; i < BQ * SK; i += 256)
            if ((i & 3) && mb[i]) odd = true;
        bool is_byte = __syncthreads_or(odd);
        const int* mi = (const int*)mask;
        for (int i = tid; i < BQ * SK; i += 256)
            g_maskBias[i] = (is_byte ? (int)mb[i] : mi[i]) ? 0.0f : NEGV;
    }
}

// ---------------------------------------------------------------------------
// Smem layout (halves units):
//   Qhs[128][72]  Qls[128][72]                      (36864 B)
//   2 stages x { Khs[64][72], Vs[64][72], bias[64]f } (2 x 18688 B)
// Total 74240 B -> 2 CTAs/SM.
// ---------------------------------------------------------------------------
#define OFF_QH    0
#define OFF_QL    (TM * KPAD)
#define OFF_ST    (2 * TM * KPAD)
#define ST_K      0
#define ST_V      (TN * KPAD)
#define ST_BIAS   (2 * TN * KPAD)
#define STAGE_HALFS (2 * TN * KPAD + 2 * TN)   // 9344
#define SMEM_HALFS (OFF_ST + 2 * STAGE_HALFS)

// cp.async f16 K/V tile + fp32 bias directly into operand layout.
static __device__ __forceinline__ void issue_tile(__half* smp, int stage, int n0,
                                                  size_t bhbase, int b, int tid) {
    __half* st = smp + OFF_ST + stage * STAGE_HALFS;
#pragma unroll
    for (int k = 0; k < 4; k++) {
        int i = tid + k * THREADS;          // 0..1023; k<2 -> K, k>=2 -> V
        int within = i & 511;
        int r = within >> 3, c = within & 7;
        const __half* src = (i < 512 ? g_k16 : g_v16) + bhbase + (size_t)(n0 + r) * DH + c * 8;
        __half* dst = st + (i < 512 ? ST_K : ST_V) + r * KPAD + c * 8;
        CP16(smem_u32(dst), src);
    }
    if (tid < 16)
        CP16(smem_u32((float*)(st + ST_BIAS) + tid * 4),
             &g_maskBias[b * SK + n0 + tid * 4]);
}

__global__ void __launch_bounds__(THREADS, 2)
fa_kernel(const float* __restrict__ q, float* __restrict__ out) {
    extern __shared__ __align__(16) __half smp[];
    __half (*Qhs)[KPAD] = (__half (*)[KPAD])(smp + OFF_QH);
    __half (*Qls)[KPAD] = (__half (*)[KPAD])(smp + OFF_QL);

    const int qt  = (SQ / TM - 1) - blockIdx.x;   // heavy tiles first
    const int bh  = blockIdx.y;
    const int b   = bh / HQ;
    const int h   = bh % HQ;
    const int hkv = h / GRP;
    const int m0  = qt * TM;
    const size_t bhbase = ((size_t)(b * HKV + hkv)) * SK * DH;

    const int tid  = threadIdx.x;
    const int lane = tid & 31;
    const int w    = tid >> 5;
    const int qd   = lane & 3;
    const int rl   = lane >> 2;
    const int g    = lane >> 3;

    const int ntiles = 2 * qt + 2;

    // kick off tile 0 loads, overlap with Q load+split
    issue_tile(smp, 0, 0, bhbase, b, tid);
    CP_COMMIT();

    const float* qg = q + ((size_t)(b * SQ + m0) * HQ + h) * DH;
    for (int i = tid; i < TM * 16; i += THREADS) {
        int r = i >> 4, f = i & 15;
        float4 v = *(const float4*)(qg + (size_t)r * HQ * DH + f * 4);
        __half h0, l0, h1, l1, h2, l2, h3, l3;
        split16(v.x, h0, l0); split16(v.y, h1, l1);
        split16(v.z, h2, l2); split16(v.w, h3, l3);
        *(__half2*)&Qhs[r][f * 4]     = __halves2half2(h0, h1);
        *(__half2*)&Qhs[r][f * 4 + 2] = __halves2half2(h2, h3);
        *(__half2*)&Qls[r][f * 4]     = __halves2half2(l0, l1);
        *(__half2*)&Qls[r][f * 4 + 2] = __halves2half2(l2, l3);
    }

    float m_lo = -1e30f, m_hi = -1e30f, l_lo = 0.0f, l_hi = 0.0f;
    float O[8][4];
#pragma unroll
    for (int j = 0; j < 8; j++)
#pragma unroll
        for (int e = 0; e < 4; e++) O[j][e] = 0.0f;

    const int r_lo = m0 + w * 16 + rl;
    const int r_hi = r_lo + 8;
    const int arow = w * 16 + (lane & 15);
    const int acol = (lane >> 4) * 8;

    for (int jt = 0; jt < ntiles; jt++) {
        const int n0 = jt * TN;
        const int stage = jt & 1;
        __half* st = smp + OFF_ST + stage * STAGE_HALFS;
        __half (*Khs)[KPAD] = (__half (*)[KPAD])(st + ST_K);
        __half (*Vs)[KPAD]  = (__half (*)[KPAD])(st + ST_V);
        float* biasS = (float*)(st + ST_BIAS);

        // tile jt landed; barrier also proves tile jt-1 (stage^1) consumed
        CP_WAIT0();
        __syncthreads();
        if (jt + 1 < ntiles) {
            issue_tile(smp, stage ^ 1, n0 + TN, bhbase, b, tid);
            CP_COMMIT();
        }

        // ---- S = Q K^T via 2-pass compensated HMMA (Qh*Kh + Ql*Kh) ----
        float S[8][4];
#pragma unroll
        for (int j = 0; j < 8; j++)
#pragma unroll
            for (int e = 0; e < 4; e++) S[j][e] = 0.0f;

#pragma unroll
        for (int ks = 0; ks < 4; ks++) {
            unsigned ah0, ah1, ah2, ah3, al0, al1, al2, al3;
            LDSM4(ah0, ah1, ah2, ah3, smem_u32(&Qhs[arow][ks * 16 + acol]));
            LDSM4(al0, al1, al2, al3, smem_u32(&Qls[arow][ks * 16 + acol]));
#pragma unroll
            for (int jp = 0; jp < 4; jp++) {
                const int brow = jp * 16 + (g >> 1) * 8 + (lane & 7);
                const int bcol = ks * 16 + (g & 1) * 8;
                unsigned bh0, bh1, bh2, bh3;
                LDSM4(bh0, bh1, bh2, bh3, smem_u32(&Khs[brow][bcol]));
                MMA16816(S[2 * jp],     ah0, ah1, ah2, ah3, bh0, bh1);
                MMA16816(S[2 * jp + 1], ah0, ah1, ah2, ah3, bh2, bh3);
                MMA16816(S[2 * jp],     al0, al1, al2, al3, bh0, bh1);
                MMA16816(S[2 * jp + 1], al0, al1, al2, al3, bh2, bh3);
            }
        }

        // ---- scale + bias (+ causal only on the last two tiles) ----
        float mx_lo = -1e30f, mx_hi = -1e30f;
        if (jt < 2 * qt) {                 // fast path: no causal masking
#pragma unroll
            for (int j = 0; j < 8; j++) {
                float2 bp = *(float2*)&biasS[j * 8 + qd * 2];
                float s0 = fmaf(S[j][0], SCALE, bp.x);
                float s1 = fmaf(S[j][1], SCALE, bp.y);
                float s2 = fmaf(S[j][2], SCALE, bp.x);
                float s3 = fmaf(S[j][3], SCALE, bp.y);
                S[j][0] = s0; S[j][1] = s1; S[j][2] = s2; S[j][3] = s3;
                mx_lo = fmaxf(mx_lo, fmaxf(s0, s1));
                mx_hi = fmaxf(mx_hi, fmaxf(s2, s3));
            }
        } else {                           // diagonal tiles: apply causal mask
#pragma unroll
            for (int j = 0; j < 8; j++) {
                float2 bp = *(float2*)&biasS[j * 8 + qd * 2];
                int c0 = n0 + j * 8 + qd * 2, c1 = c0 + 1;
                float s0 = fmaf(S[j][0], SCALE, bp.x);
                float s1 = fmaf(S[j][1], SCALE, bp.y);
                float s2 = fmaf(S[j][2], SCALE, bp.x);
                float s3 = fmaf(S[j][3], SCALE, bp.y);
                if (c0 > r_lo) s0 = NEGV;
                if (c1 > r_lo) s1 = NEGV;
                if (c0 > r_hi) s2 = NEGV;
                if (c1 > r_hi) s3 = NEGV;
                S[j][0] = s0; S[j][1] = s1; S[j][2] = s2; S[j][3] = s3;
                mx_lo = fmaxf(mx_lo, fmaxf(s0, s1));
                mx_hi = fmaxf(mx_hi, fmaxf(s2, s3));
            }
        }
        mx_lo = fmaxf(mx_lo, __shfl_xor_sync(0xffffffffu, mx_lo, 1));
        mx_lo = fmaxf(mx_lo, __shfl_xor_sync(0xffffffffu, mx_lo, 2));
        mx_hi = fmaxf(mx_hi, __shfl_xor_sync(0xffffffffu, mx_hi, 1));
        mx_hi = fmaxf(mx_hi, __shfl_xor_sync(0xffffffffu, mx_hi, 2));

        float mn_lo = fmaxf(m_lo, mx_lo), mn_hi = fmaxf(m_hi, mx_hi);

        // ---- alpha rescale, skipped when no row in the warp has a new max ----
        if (__any_sync(0xffffffffu, (mn_lo > m_lo) || (mn_hi > m_hi))) {
            float al = exp2m((m_lo - mn_lo) * LOG2E);
            float ah = exp2m((m_hi - mn_hi) * LOG2E);
            l_lo *= al; l_hi *= ah;
#pragma unroll
            for (int j = 0; j < 8; j++) {
                O[j][0] *= al; O[j][1] *= al;
                O[j][2] *= ah; O[j][3] *= ah;
            }
            m_lo = mn_lo; m_hi = mn_hi;
        }

        float base_lo = -m_lo * LOG2E, base_hi = -m_hi * LOG2E;
        float sum_lo = 0.0f, sum_hi = 0.0f;
        unsigned pf[8][2];
#pragma unroll
        for (int j = 0; j < 8; j++) {
            float p0 = exp2m(fmaf(S[j][0], LOG2E, base_lo));
            float p1 = exp2m(fmaf(S[j][1], LOG2E, base_lo));
            float p2 = exp2m(fmaf(S[j][2], LOG2E, base_hi));
            float p3 = exp2m(fmaf(S[j][3], LOG2E, base_hi));
            sum_lo += p0 + p1;
            sum_hi += p2 + p3;
            __half2 hl = __floats2half2_rn(p0, p1);
            __half2 hh = __floats2half2_rn(p2, p3);
            pf[j][0] = *(unsigned*)&hl;
            pf[j][1] = *(unsigned*)&hh;
        }
        sum_lo += __shfl_xor_sync(0xffffffffu, sum_lo, 1);
        sum_lo += __shfl_xor_sync(0xffffffffu, sum_lo, 2);
        sum_hi += __shfl_xor_sync(0xffffffffu, sum_hi, 1);
        sum_hi += __shfl_xor_sync(0xffffffffu, sum_hi, 2);
        l_lo += sum_lo;
        l_hi += sum_hi;

        // ---- O += P V via HMMA (P frags from registers) ----
#pragma unroll
        for (int ks = 0; ks < 4; ks++) {
            unsigned A0 = pf[2 * ks][0], A1 = pf[2 * ks][1];
            unsigned A2 = pf[2 * ks + 1][0], A3 = pf[2 * ks + 1][1];
#pragma unroll
            for (int dp = 0; dp < 4; dp++) {
                unsigned b0, b1, b2, b3;
                unsigned vaddr = smem_u32(&Vs[ks * 16 + (g & 1) * 8 + (lane & 7)][(dp * 2 + (g >> 1)) * 8]);
                LDSM4T(b0, b1, b2, b3, vaddr);
                MMA16816(O[2 * dp],     A0, A1, A2, A3, b0, b1);
                MMA16816(O[2 * dp + 1], A0, A1, A2, A3, b2, b3);
            }
        }
    }

    // ---- epilogue: tail correction over UNPROCESSED cols only ----
    const int n_proc = ntiles * TN;   // m0 + 128, multiple of 128
    bool need = (m_lo < -5000.0f) || (m_hi < -5000.0f);
    if (__any_sync(0xffffffffu, need) && n_proc < SK) {
        float mf_lo = fmaxf(m_lo, NEGV), mf_hi = fmaxf(m_hi, NEGV);
        float al = __expf(m_lo - mf_lo), ah = __expf(m_hi - mf_hi);
        float te_lo = __expf(NEGV - mf_lo), te_hi = __expf(NEGV - mf_hi);
        float ntail = (float)(SK - n_proc);
        l_lo = l_lo * al + ntail * te_lo;
        l_hi = l_hi * ah + ntail * te_hi;
        const int blk0 = n_proc >> 7;
        const int bhk  = b * HKV + hkv;
#pragma unroll
        for (int j = 0; j < 8; j++) {
            int d0 = j * 8 + qd * 2;
            float t0 = 0.0f, t1 = 0.0f;
            for (int bb = blk0; bb < 16; bb++) {
                t0 += g_bsum[bhk][bb][d0];
                t1 += g_bsum[bhk][bb][d0 + 1];
            }
            O[j][0] = O[j][0] * al + te_lo * t0;
            O[j][1] = O[j][1] * al + te_lo * t1;
            O[j][2] = O[j][2] * ah + te_hi * t0;
            O[j][3] = O[j][3] * ah + te_hi * t1;
        }
    }

    float il = 1.0f / l_lo, ih = 1.0f / l_hi;
    float* po  = out + ((size_t)(b * SQ + r_lo) * HQ + h) * DH;
    float* po2 = out + ((size_t)(b * SQ + r_hi) * HQ + h) * DH;
#pragma unroll
    for (int j = 0; j < 8; j++) {
        int d0 = j * 8 + qd * 2;
        *(float2*)&po[d0]  = make_float2(O[j][0] * il, O[j][1] * il);
        *(float2*)&po2[d0] = make_float2(O[j][2] * ih, O[j][3] * ih);
    }
}

// ---------------------------------------------------------------------------
extern "C" void kernel_launch(void* const* d_in, const int* in_sizes, int n_in,
                              void* d_out, int out_size) {
    const float* q    = (const float*)d_in[0];
    const float* kv   = (const float*)d_in[1];
    const void*  mask = d_in[2];
    float* out = (float*)d_out;

    const int smem_bytes = SMEM_HALFS * sizeof(__half);   // 74240
    static bool attr_set = false;
    if (!attr_set) {
        cudaFuncSetAttribute(fa_kernel,
                             cudaFuncAttributeMaxDynamicSharedMemorySize,
                             smem_bytes);
        attr_set = true;
    }

    prologue_kernel<<<640, 256>>>(kv, mask);
    dim3 grid(SQ / TM, BQ * HQ);
    fa_kernel<<<grid, THREADS, smem_bytes>>>(q, out);
}